// round 4
// baseline (speedup 1.0000x reference)
#include <cuda_runtime.h>

#define Hh 192
#define Ww 192

__device__ float g_att[8 * 9 * 192 * 192];   // [b][p][y][x]
__device__ float g_pooled[8 * 32];
__device__ float g_bias[8 * 32];

typedef unsigned long long ull;

__device__ __forceinline__ ull pk2(float lo, float hi) {
    ull r; asm("mov.b64 %0,{%1,%2};" : "=l"(r) : "f"(lo), "f"(hi)); return r;
}
__device__ __forceinline__ void upk2(ull v, float& lo, float& hi) {
    asm("mov.b64 {%0,%1},%2;" : "=f"(lo), "=f"(hi) : "l"(v));
}
__device__ __forceinline__ ull fma2(ull a, ull b, ull c) {
    ull r; asm("fma.rn.f32x2 %0,%1,%2,%3;" : "=l"(r) : "l"(a), "l"(b), "l"(c)); return r;
}
__device__ __forceinline__ ull mul2(ull a, ull b) {
    ull r; asm("mul.rn.f32x2 %0,%1,%2;" : "=l"(r) : "l"(a), "l"(b)); return r;
}

// ---------------------------------------------------------------------------
// Kernel 1: global average pool.
// ---------------------------------------------------------------------------
__global__ void pooled_kernel(const float* __restrict__ x) {
    int bn = blockIdx.x;
    const float* p = x + (size_t)bn * Hh * Ww;
    float s = 0.f;
    for (int i = threadIdx.x; i < Hh * Ww; i += 256) s += p[i];
    __shared__ float red[256];
    red[threadIdx.x] = s;
    __syncthreads();
    for (int o = 128; o > 0; o >>= 1) {
        if (threadIdx.x < o) red[threadIdx.x] += red[threadIdx.x + o];
        __syncthreads();
    }
    if (threadIdx.x == 0) g_pooled[bn] = red[0] * (1.f / (Hh * Ww));
}

// ---------------------------------------------------------------------------
// Kernel 2: bias MLP.
// ---------------------------------------------------------------------------
__global__ void bias_kernel(const float* __restrict__ b1w, const float* __restrict__ b1b,
                            const float* __restrict__ b2w, const float* __restrict__ b2b) {
    __shared__ float h[8 * 32];
    int t = threadIdx.x;
    int b = t >> 5, k = t & 31;
    float s = b1b[k];
    for (int n = 0; n < 32; n++) s += g_pooled[b * 32 + n] * b1w[k * 32 + n];
    h[t] = fmaxf(s, 0.f);
    __syncthreads();
    int m = k;
    float s2 = b2b[m];
    for (int kk = 0; kk < 32; kk++) s2 += h[b * 32 + kk] * b2w[m * 32 + kk];
    g_bias[t] = s2;
}

// ---------------------------------------------------------------------------
// Kernel 3: attention stack — f32x2 over output-channel pairs (unchanged R3).
// ---------------------------------------------------------------------------
#define AXS 40
__global__ __launch_bounds__(256, 2)
void attn_kernel(const float* __restrict__ x, const float* __restrict__ a1w,
                 const float* __restrict__ a1b, const float* __restrict__ a2w,
                 const float* __restrict__ a2b, const float* __restrict__ a3w,
                 const float* __restrict__ a3b) {
    extern __shared__ float sm[];
    float* xs = sm;                  // 32*18*40 = 23040
    float* w1p = xs + 23040;         // 32*9*10 = 2880  [n][t][o(pad10)]
    float* w2 = w1p + 2880;          // 81
    float* w3 = w2 + 81;             // 81
    float* bb1 = w3 + 81;            // 9
    float* bb2 = bb1 + 9;            // 9
    float* bb3 = bb2 + 9;            // 9

    int b = blockIdx.z;
    int y0 = blockIdx.y * 16, x0 = blockIdx.x * 32;
    int tid = threadIdx.x;

    for (int i = tid; i < 2880; i += 256) {
        int nt = i / 10, o = i % 10;
        w1p[i] = (o < 9) ? a1w[o * 288 + nt] : 0.f;
    }
    if (tid < 81) { w2[tid] = a2w[tid]; w3[tid] = a3w[tid]; }
    if (tid < 9) { bb1[tid] = a1b[tid]; bb2[tid] = a2b[tid]; bb3[tid] = a3b[tid]; }

    const float* xb = x + (size_t)b * 32 * Hh * Ww;
    for (int i = tid; i < 32 * 18 * 34; i += 256) {
        int n = i / (18 * 34);
        int r = i % (18 * 34);
        int yy = r / 34, xx = r % 34;
        int gy = y0 + yy - 1, gx = x0 + xx - 1;
        float v = 0.f;
        if ((unsigned)gy < Hh && (unsigned)gx < Ww) v = xb[(n * Hh + gy) * Ww + gx];
        xs[(n * 18 + yy) * AXS + xx] = v;
    }
    __syncthreads();

    int w = tid >> 5;
    int half = (tid >> 4) & 1;
    int c = tid & 15;
    int py = (w & 1) + (w >> 1) * 4 + 2 * half;

    ull acc[2][5];
#pragma unroll
    for (int j = 0; j < 2; j++)
#pragma unroll
        for (int q = 0; q < 5; q++) acc[j][q] = 0ull;

    for (int n = 0; n < 32; n++) {
        const float* xr = xs + (n * 18 + py) * AXS + c;
        const ull* wn = (const ull*)(w1p + n * 90);
#pragma unroll
        for (int t = 0; t < 9; t++) {
            const int ki = t / 3, kj = t % 3;
            float v0 = xr[ki * AXS + kj];
            float v1 = xr[ki * AXS + kj + 16];
            ull A = pk2(v0, v0);
            ull B = pk2(v1, v1);
            const ull* wt = wn + t * 5;
#pragma unroll
            for (int q = 0; q < 5; q++) {
                ull W = wt[q];
                acc[0][q] = fma2(W, A, acc[0][q]);
                acc[1][q] = fma2(W, B, acc[1][q]);
            }
        }
    }

    int gy = y0 + py;
#pragma unroll
    for (int j = 0; j < 2; j++) {
        int gx = x0 + c + 16 * j;
        float u[9], z[9], dummy;
#pragma unroll
        for (int q = 0; q < 4; q++) upk2(acc[j][q], u[2 * q], u[2 * q + 1]);
        upk2(acc[j][4], u[8], dummy);
#pragma unroll
        for (int o = 0; o < 9; o++) u[o] = fmaxf(u[o] + bb1[o], 0.f);
#pragma unroll
        for (int o2 = 0; o2 < 9; o2++) {
            float s = bb2[o2];
#pragma unroll
            for (int o = 0; o < 9; o++) s += w2[o2 * 9 + o] * u[o];
            z[o2] = fmaxf(s, 0.f);
        }
#pragma unroll
        for (int o3 = 0; o3 < 9; o3++) {
            float s = bb3[o3];
#pragma unroll
            for (int o2 = 0; o2 < 9; o2++) s += w3[o3 * 9 + o2] * z[o2];
            float att = 1.f / (1.f + __expf(-s));
            g_att[((b * 9 + o3) * Hh + gy) * Ww + gx] = att;
        }
    }
}

// ---------------------------------------------------------------------------
// Kernel 4: main conv — 16x8 tile, warp = 4-m group, 16 f32x2 accs/thread.
// smem 67KB -> 3 CTAs/SM; reg target 84 (launch_bounds 256,3).
// xs: [n2][yy][xx][e], row stride 20 ull; lane addr 20*py+c distinct mod 32.
// ---------------------------------------------------------------------------
__global__ __launch_bounds__(256, 3)
void main_kernel(const float* __restrict__ x, const float* __restrict__ weight,
                 float* __restrict__ out) {
    extern __shared__ float sm[];
    float* xs = sm;                 // 16*10*40 = 6400
    float* ws = xs + 6400;          // 9*16*32*2 = 9216  [p][n2][m][e]
    float* atts = ws + 9216;        // 9*8*16 = 1152

    int b = blockIdx.z;
    int y0 = blockIdx.y * 8, x0 = blockIdx.x * 16;
    int tid = threadIdx.x;

    const float* xb = x + (size_t)b * 32 * Hh * Ww;
    for (int i = tid; i < 32 * 10 * 18; i += 256) {
        int n = i / 180;
        int r = i % 180;
        int yy = r / 18, xx = r % 18;
        int gy = y0 + yy - 1, gx = x0 + xx - 1;
        float v = 0.f;
        if ((unsigned)gy < Hh && (unsigned)gx < Ww) v = xb[(n * Hh + gy) * Ww + gx];
        xs[(((n >> 1) * 10 + yy) * 20 + xx) * 2 + (n & 1)] = v;
    }
    for (int i = tid; i < 9216; i += 256) {
        int q = i >> 2;
        int c4 = i & 3;
        int p = q >> 8;
        int n2 = (q >> 4) & 15;
        int m2 = q & 15;
        int m = 2 * m2 + (c4 >> 1);
        int n = 2 * n2 + (c4 & 1);
        ws[i] = weight[(m * 32 + n) * 9 + p];
    }
    for (int i = tid; i < 1152; i += 256) {
        int p = i >> 7;
        int r = i & 127;
        int yy = r >> 4, xx = r & 15;
        atts[i] = g_att[((b * 9 + p) * Hh + y0 + yy) * Ww + x0 + xx];
    }
    __syncthreads();

    int mg = tid >> 5;        // warp id 0..7 -> m-group
    int lane = tid & 31;
    int m0 = mg * 4;
    int py = lane >> 2;       // 0..7
    int c = lane & 3;         // px = c + 4*j

    const ull* xs64 = (const ull*)xs;   // [n2*200 + yy*20 + xx]
    const ull* ws64 = (const ull*)ws;   // [p*512 + n2*32 + m]

    ull acc[4][4];
#pragma unroll
    for (int mm = 0; mm < 4; mm++)
#pragma unroll
        for (int j = 0; j < 4; j++) acc[mm][j] = 0ull;

#pragma unroll
    for (int p = 0; p < 9; p++) {
        int ki = p / 3, kj = p % 3;
        ull att2[4];
#pragma unroll
        for (int j = 0; j < 4; j++) {
            float a = atts[(p * 8 + py) * 16 + c + 4 * j];
            att2[j] = pk2(a, a);
        }
        const ull* wp = ws64 + p * 512 + m0;
        int xbase = (py + ki) * 20 + c + kj;
#pragma unroll 4
        for (int n2 = 0; n2 < 16; n2++) {
            const ull* xr = xs64 + n2 * 200 + xbase;
            ull v0 = mul2(xr[0],  att2[0]);
            ull v1 = mul2(xr[4],  att2[1]);
            ull v2 = mul2(xr[8],  att2[2]);
            ull v3 = mul2(xr[12], att2[3]);
            const ulonglong2* wr2 = (const ulonglong2*)(wp + n2 * 32);
            ulonglong2 w01 = wr2[0];
            ulonglong2 w23 = wr2[1];
            acc[0][0] = fma2(w01.x, v0, acc[0][0]); acc[0][1] = fma2(w01.x, v1, acc[0][1]);
            acc[0][2] = fma2(w01.x, v2, acc[0][2]); acc[0][3] = fma2(w01.x, v3, acc[0][3]);
            acc[1][0] = fma2(w01.y, v0, acc[1][0]); acc[1][1] = fma2(w01.y, v1, acc[1][1]);
            acc[1][2] = fma2(w01.y, v2, acc[1][2]); acc[1][3] = fma2(w01.y, v3, acc[1][3]);
            acc[2][0] = fma2(w23.x, v0, acc[2][0]); acc[2][1] = fma2(w23.x, v1, acc[2][1]);
            acc[2][2] = fma2(w23.x, v2, acc[2][2]); acc[2][3] = fma2(w23.x, v3, acc[2][3]);
            acc[3][0] = fma2(w23.y, v0, acc[3][0]); acc[3][1] = fma2(w23.y, v1, acc[3][1]);
            acc[3][2] = fma2(w23.y, v2, acc[3][2]); acc[3][3] = fma2(w23.y, v3, acc[3][3]);
        }
    }

    int gy = y0 + py;
#pragma unroll
    for (int mm = 0; mm < 4; mm++) {
        float bv = g_bias[b * 32 + m0 + mm];
        float* orow = out + ((size_t)(b * 32 + m0 + mm) * Hh + gy) * Ww + x0 + c;
#pragma unroll
        for (int j = 0; j < 4; j++) {
            float lo, hi;
            upk2(acc[mm][j], lo, hi);
            orow[4 * j] = lo + hi + bv;
        }
    }
}

// ---------------------------------------------------------------------------
extern "C" void kernel_launch(void* const* d_in, const int* in_sizes, int n_in,
                              void* d_out, int out_size) {
    const float* x   = (const float*)d_in[0];
    const float* a1w = (const float*)d_in[1];
    const float* a1b = (const float*)d_in[2];
    const float* a2w = (const float*)d_in[3];
    const float* a2b = (const float*)d_in[4];
    const float* a3w = (const float*)d_in[5];
    const float* a3b = (const float*)d_in[6];
    const float* b1w = (const float*)d_in[7];
    const float* b1b = (const float*)d_in[8];
    const float* b2w = (const float*)d_in[9];
    const float* b2b = (const float*)d_in[10];
    const float* wgt = (const float*)d_in[11];
    float* out = (float*)d_out;

    pooled_kernel<<<256, 256>>>(x);
    bias_kernel<<<1, 256>>>(b1w, b1b, b2w, b2b);

    int smA = (23040 + 2880 + 81 + 81 + 9 + 9 + 9) * (int)sizeof(float);
    cudaFuncSetAttribute(attn_kernel, cudaFuncAttributeMaxDynamicSharedMemorySize, smA);
    attn_kernel<<<dim3(6, 12, 8), 256, smA>>>(x, a1w, a1b, a2w, a2b, a3w, a3b);

    int smM = (6400 + 9216 + 1152) * (int)sizeof(float);
    cudaFuncSetAttribute(main_kernel, cudaFuncAttributeMaxDynamicSharedMemorySize, smM);
    main_kernel<<<dim3(12, 24, 8), 256, smM>>>(x, wgt, out);
}

// round 5
// speedup vs baseline: 2.0654x; 2.0654x over previous
#include <cuda_runtime.h>
#include <cstdint>

#define Hh 192
#define Ww 192

__device__ float g_att[8 * 9 * 192 * 192];   // [b][p][y][x]
__device__ float g_pooled[8 * 32];
__device__ float g_bias[8 * 32];

typedef unsigned long long ull;

__device__ __forceinline__ ull pk2(float lo, float hi) {
    ull r; asm("mov.b64 %0,{%1,%2};" : "=l"(r) : "f"(lo), "f"(hi)); return r;
}
__device__ __forceinline__ void upk2(ull v, float& lo, float& hi) {
    asm("mov.b64 {%0,%1},%2;" : "=f"(lo), "=f"(hi) : "l"(v));
}
__device__ __forceinline__ ull fma2(ull a, ull b, ull c) {
    ull r; asm("fma.rn.f32x2 %0,%1,%2,%3;" : "=l"(r) : "l"(a), "l"(b), "l"(c)); return r;
}
__device__ __forceinline__ uint32_t cvt_tf32(float x) {
    uint32_t r; asm("cvt.rna.tf32.f32 %0, %1;" : "=r"(r) : "f"(x)); return r;
}
__device__ __forceinline__ void mma_tf32(float d[4], const uint32_t a[4], const uint32_t b[2]) {
    asm("mma.sync.aligned.m16n8k8.row.col.f32.tf32.tf32.f32 "
        "{%0,%1,%2,%3},{%4,%5,%6,%7},{%8,%9},{%0,%1,%2,%3};"
        : "+f"(d[0]), "+f"(d[1]), "+f"(d[2]), "+f"(d[3])
        : "r"(a[0]), "r"(a[1]), "r"(a[2]), "r"(a[3]), "r"(b[0]), "r"(b[1]));
}

// ---------------------------------------------------------------------------
// Kernel 1: global average pool.
// ---------------------------------------------------------------------------
__global__ void pooled_kernel(const float* __restrict__ x) {
    int bn = blockIdx.x;
    const float* p = x + (size_t)bn * Hh * Ww;
    float s = 0.f;
    for (int i = threadIdx.x; i < Hh * Ww; i += 256) s += p[i];
    __shared__ float red[256];
    red[threadIdx.x] = s;
    __syncthreads();
    for (int o = 128; o > 0; o >>= 1) {
        if (threadIdx.x < o) red[threadIdx.x] += red[threadIdx.x + o];
        __syncthreads();
    }
    if (threadIdx.x == 0) g_pooled[bn] = red[0] * (1.f / (Hh * Ww));
}

// ---------------------------------------------------------------------------
// Kernel 2: bias MLP.
// ---------------------------------------------------------------------------
__global__ void bias_kernel(const float* __restrict__ b1w, const float* __restrict__ b1b,
                            const float* __restrict__ b2w, const float* __restrict__ b2b) {
    __shared__ float h[8 * 32];
    int t = threadIdx.x;
    int b = t >> 5, k = t & 31;
    float s = b1b[k];
    for (int n = 0; n < 32; n++) s += g_pooled[b * 32 + n] * b1w[k * 32 + n];
    h[t] = fmaxf(s, 0.f);
    __syncthreads();
    int m = k;
    float s2 = b2b[m];
    for (int kk = 0; kk < 32; kk++) s2 += h[b * 32 + kk] * b2w[m * 32 + kk];
    g_bias[t] = s2;
}

// ---------------------------------------------------------------------------
// Kernel 3: attention stack — f32x2 over output-channel pairs (R3 version).
// ---------------------------------------------------------------------------
#define AXS 40
__global__ __launch_bounds__(256, 2)
void attn_kernel(const float* __restrict__ x, const float* __restrict__ a1w,
                 const float* __restrict__ a1b, const float* __restrict__ a2w,
                 const float* __restrict__ a2b, const float* __restrict__ a3w,
                 const float* __restrict__ a3b) {
    extern __shared__ float sm[];
    float* xs = sm;                  // 32*18*40 = 23040
    float* w1p = xs + 23040;         // 2880
    float* w2 = w1p + 2880;
    float* w3 = w2 + 81;
    float* bb1 = w3 + 81;
    float* bb2 = bb1 + 9;
    float* bb3 = bb2 + 9;

    int b = blockIdx.z;
    int y0 = blockIdx.y * 16, x0 = blockIdx.x * 32;
    int tid = threadIdx.x;

    for (int i = tid; i < 2880; i += 256) {
        int nt = i / 10, o = i % 10;
        w1p[i] = (o < 9) ? a1w[o * 288 + nt] : 0.f;
    }
    if (tid < 81) { w2[tid] = a2w[tid]; w3[tid] = a3w[tid]; }
    if (tid < 9) { bb1[tid] = a1b[tid]; bb2[tid] = a2b[tid]; bb3[tid] = a3b[tid]; }

    const float* xb = x + (size_t)b * 32 * Hh * Ww;
    for (int i = tid; i < 32 * 18 * 34; i += 256) {
        int n = i / (18 * 34);
        int r = i % (18 * 34);
        int yy = r / 34, xx = r % 34;
        int gy = y0 + yy - 1, gx = x0 + xx - 1;
        float v = 0.f;
        if ((unsigned)gy < Hh && (unsigned)gx < Ww) v = xb[(n * Hh + gy) * Ww + gx];
        xs[(n * 18 + yy) * AXS + xx] = v;
    }
    __syncthreads();

    int w = tid >> 5;
    int half = (tid >> 4) & 1;
    int c = tid & 15;
    int py = (w & 1) + (w >> 1) * 4 + 2 * half;

    ull acc[2][5];
#pragma unroll
    for (int j = 0; j < 2; j++)
#pragma unroll
        for (int q = 0; q < 5; q++) acc[j][q] = 0ull;

    for (int n = 0; n < 32; n++) {
        const float* xr = xs + (n * 18 + py) * AXS + c;
        const ull* wn = (const ull*)(w1p + n * 90);
#pragma unroll
        for (int t = 0; t < 9; t++) {
            const int ki = t / 3, kj = t % 3;
            float v0 = xr[ki * AXS + kj];
            float v1 = xr[ki * AXS + kj + 16];
            ull A = pk2(v0, v0);
            ull B = pk2(v1, v1);
            const ull* wt = wn + t * 5;
#pragma unroll
            for (int q = 0; q < 5; q++) {
                ull W = wt[q];
                acc[0][q] = fma2(W, A, acc[0][q]);
                acc[1][q] = fma2(W, B, acc[1][q]);
            }
        }
    }

    int gy = y0 + py;
#pragma unroll
    for (int j = 0; j < 2; j++) {
        int gx = x0 + c + 16 * j;
        float u[9], z[9], dummy;
#pragma unroll
        for (int q = 0; q < 4; q++) upk2(acc[j][q], u[2 * q], u[2 * q + 1]);
        upk2(acc[j][4], u[8], dummy);
#pragma unroll
        for (int o = 0; o < 9; o++) u[o] = fmaxf(u[o] + bb1[o], 0.f);
#pragma unroll
        for (int o2 = 0; o2 < 9; o2++) {
            float s = bb2[o2];
#pragma unroll
            for (int o = 0; o < 9; o++) s += w2[o2 * 9 + o] * u[o];
            z[o2] = fmaxf(s, 0.f);
        }
#pragma unroll
        for (int o3 = 0; o3 < 9; o3++) {
            float s = bb3[o3];
#pragma unroll
            for (int o2 = 0; o2 < 9; o2++) s += w3[o3 * 9 + o2] * z[o2];
            float att = 1.f / (1.f + __expf(-s));
            g_att[((b * 9 + o3) * Hh + gy) * Ww + gx] = att;
        }
    }
}

// ---------------------------------------------------------------------------
// Kernel 4: main conv via tf32 mma.sync m16n8k8.
// Per 16x16 pixel tile: D[256px, 32m] GEMM with K=288=(p,n); per-p K=32
// sub-GEMM into G (tensor, tf32), then D += att[p,px] * G in exact fp32.
// Warp w: tile rows {2w, 2w+1}, each an m16 row-frag (frag row r = x coord).
// 4 tiles per CTA (weights loaded once). Grid 288 = one wave @ 2 CTA/SM.
// xs: tf32-rounded, n-stride 360 (banks 8*k0+r). ws: [p][m][n] n-stride 36
// (banks 4*r+k0). Both conflict-free for the fragment load patterns.
// ---------------------------------------------------------------------------
__global__ __launch_bounds__(256, 2)
void main_kernel(const float* __restrict__ x, const float* __restrict__ weight,
                 float* __restrict__ out) {
    extern __shared__ uint32_t smu[];
    uint32_t* xs = smu;                       // 32*18*20 = 11520
    uint32_t* ws = smu + 11520;               // 9*32*36  = 10368
    float* atts = (float*)(smu + 11520 + 10368);  // 9*16*16 = 2304
    float* sbias = atts + 2304;               // 32

    int tid = threadIdx.x;

    // weight fill (once per CTA): ws[p][m*36+n] = tf32(weight[m][n][p])
    for (int i = tid; i < 9216; i += 256) {
        int p = i >> 10;
        int r = i & 1023;
        int m = r >> 5;
        int n = r & 31;
        ws[p * 1152 + m * 36 + n] = cvt_tf32(weight[(m * 32 + n) * 9 + p]);
    }

    int wid = tid >> 5, lane = tid & 31;
    int r4 = lane >> 2, k0 = lane & 3;

    int tile0 = blockIdx.x * 4;
    for (int t = 0; t < 4; t++) {
        int tile = tile0 + t;
        int b = tile / 144;
        int rr = tile % 144;
        int y0 = (rr / 12) * 16, x0 = (rr % 12) * 16;

        __syncthreads();   // ws ready (t=0) / prev tile mainloop done (t>0)

        const float* xb = x + (size_t)b * 32 * Hh * Ww;
        for (int i = tid; i < 32 * 18 * 18; i += 256) {
            int n = i / 324;
            int r = i % 324;
            int yy = r / 18, xx = r % 18;
            int gy = y0 + yy - 1, gx = x0 + xx - 1;
            float v = 0.f;
            if ((unsigned)gy < Hh && (unsigned)gx < Ww) v = xb[(n * Hh + gy) * Ww + gx];
            xs[n * 360 + yy * 20 + xx] = cvt_tf32(v);
        }
        for (int i = tid; i < 2304; i += 256) {
            int p = i >> 8;
            int r = i & 255;
            int yy = r >> 4, xx = r & 15;
            atts[i] = g_att[((b * 9 + p) * Hh + y0 + yy) * Ww + x0 + xx];
        }
        if (tid < 32) sbias[tid] = g_bias[b * 32 + tid];
        __syncthreads();

        // mainloop
        float D[2][4][4];
#pragma unroll
        for (int f = 0; f < 2; f++)
#pragma unroll
            for (int mc = 0; mc < 4; mc++)
#pragma unroll
                for (int e = 0; e < 4; e++) D[f][mc][e] = 0.f;

        int yA = 2 * wid, yB = 2 * wid + 1;

#pragma unroll
        for (int p = 0; p < 9; p++) {
            const int ki = p / 3, kj = p % 3;
            float G[2][4][4];
#pragma unroll
            for (int f = 0; f < 2; f++)
#pragma unroll
                for (int mc = 0; mc < 4; mc++)
#pragma unroll
                    for (int e = 0; e < 4; e++) G[f][mc][e] = 0.f;

            const uint32_t* wsP = ws + p * 1152;
            const uint32_t* xbase0 = xs + k0 * 360 + (yA + ki) * 20 + r4 + kj;
            const uint32_t* xbase1 = xbase0 + 20;   // yB = yA + 1
#pragma unroll
            for (int q = 0; q < 4; q++) {
                const uint32_t* xc0 = xbase0 + q * 2880;   // n0 = 8q + k0
                const uint32_t* xc1 = xbase1 + q * 2880;
                uint32_t a0[4], a1[4];
                a0[0] = xc0[0];        a0[1] = xc0[8];
                a0[2] = xc0[4 * 360];  a0[3] = xc0[4 * 360 + 8];
                a1[0] = xc1[0];        a1[1] = xc1[8];
                a1[2] = xc1[4 * 360];  a1[3] = xc1[4 * 360 + 8];
                int n0 = 8 * q + k0;
                const uint32_t* wq = wsP + r4 * 36 + n0;
#pragma unroll
                for (int mc = 0; mc < 4; mc++) {
                    uint32_t bb[2];
                    bb[0] = wq[mc * 288];        // m = mc*8 + r4, n0
                    bb[1] = wq[mc * 288 + 4];    // n0 + 4
                    mma_tf32(G[0][mc], a0, bb);
                    mma_tf32(G[1][mc], a1, bb);
                }
            }
            // exact fp32 attention merge
#pragma unroll
            for (int f = 0; f < 2; f++) {
                int yy = yA + f;
                float attA = atts[(p * 16 + yy) * 16 + r4];
                float attB = atts[(p * 16 + yy) * 16 + r4 + 8];
#pragma unroll
                for (int mc = 0; mc < 4; mc++) {
                    D[f][mc][0] += attA * G[f][mc][0];
                    D[f][mc][1] += attA * G[f][mc][1];
                    D[f][mc][2] += attB * G[f][mc][2];
                    D[f][mc][3] += attB * G[f][mc][3];
                }
            }
        }

        // epilogue: c0:(x=r4, m=2k0) c1:(x=r4, m=2k0+1) c2:(x=r4+8,m) c3:(x=r4+8,m+1)
#pragma unroll
        for (int f = 0; f < 2; f++) {
            int gy = y0 + yA + f;
#pragma unroll
            for (int mc = 0; mc < 4; mc++) {
                int m = mc * 8 + 2 * k0;
                float bv0 = sbias[m], bv1 = sbias[m + 1];
                float* o0 = out + ((size_t)(b * 32 + m) * Hh + gy) * Ww + x0;
                float* o1 = o0 + (size_t)Hh * Ww;
                o0[r4]     = D[f][mc][0] + bv0;
                o1[r4]     = D[f][mc][1] + bv1;
                o0[r4 + 8] = D[f][mc][2] + bv0;
                o1[r4 + 8] = D[f][mc][3] + bv1;
            }
        }
    }
}

// ---------------------------------------------------------------------------
extern "C" void kernel_launch(void* const* d_in, const int* in_sizes, int n_in,
                              void* d_out, int out_size) {
    const float* x   = (const float*)d_in[0];
    const float* a1w = (const float*)d_in[1];
    const float* a1b = (const float*)d_in[2];
    const float* a2w = (const float*)d_in[3];
    const float* a2b = (const float*)d_in[4];
    const float* a3w = (const float*)d_in[5];
    const float* a3b = (const float*)d_in[6];
    const float* b1w = (const float*)d_in[7];
    const float* b1b = (const float*)d_in[8];
    const float* b2w = (const float*)d_in[9];
    const float* b2b = (const float*)d_in[10];
    const float* wgt = (const float*)d_in[11];
    float* out = (float*)d_out;

    pooled_kernel<<<256, 256>>>(x);
    bias_kernel<<<1, 256>>>(b1w, b1b, b2w, b2b);

    int smA = (23040 + 2880 + 81 + 81 + 9 + 9 + 9) * (int)sizeof(float);
    cudaFuncSetAttribute(attn_kernel, cudaFuncAttributeMaxDynamicSharedMemorySize, smA);
    attn_kernel<<<dim3(6, 12, 8), 256, smA>>>(x, a1w, a1b, a2w, a2b, a3w, a3b);

    int smM = (11520 + 10368 + 2304 + 32) * (int)sizeof(float);
    cudaFuncSetAttribute(main_kernel, cudaFuncAttributeMaxDynamicSharedMemorySize, smM);
    main_kernel<<<288, 256, smM>>>(x, wgt, out);
}

// round 6
// speedup vs baseline: 2.3527x; 1.1391x over previous
#include <cuda_runtime.h>
#include <cstdint>

#define Hh 192
#define Ww 192

__device__ float g_att[8 * 9 * 192 * 192];   // [b][p][y][x]
__device__ float g_pooled[8 * 32];
__device__ float g_bias[8 * 32];

typedef unsigned long long ull;

__device__ __forceinline__ uint32_t cvt_tf32(float x) {
    uint32_t r; asm("cvt.rna.tf32.f32 %0, %1;" : "=r"(r) : "f"(x)); return r;
}
__device__ __forceinline__ void mma_tf32(float d[4], const uint32_t a[4], const uint32_t b[2]) {
    asm("mma.sync.aligned.m16n8k8.row.col.f32.tf32.tf32.f32 "
        "{%0,%1,%2,%3},{%4,%5,%6,%7},{%8,%9},{%0,%1,%2,%3};"
        : "+f"(d[0]), "+f"(d[1]), "+f"(d[2]), "+f"(d[3])
        : "r"(a[0]), "r"(a[1]), "r"(a[2]), "r"(a[3]), "r"(b[0]), "r"(b[1]));
}

// ---------------------------------------------------------------------------
// Kernel 1: global average pool.
// ---------------------------------------------------------------------------
__global__ void pooled_kernel(const float* __restrict__ x) {
    int bn = blockIdx.x;
    const float* p = x + (size_t)bn * Hh * Ww;
    float s = 0.f;
    for (int i = threadIdx.x; i < Hh * Ww; i += 256) s += p[i];
    __shared__ float red[256];
    red[threadIdx.x] = s;
    __syncthreads();
    for (int o = 128; o > 0; o >>= 1) {
        if (threadIdx.x < o) red[threadIdx.x] += red[threadIdx.x + o];
        __syncthreads();
    }
    if (threadIdx.x == 0) g_pooled[bn] = red[0] * (1.f / (Hh * Ww));
}

// ---------------------------------------------------------------------------
// Kernel 2: bias MLP.
// ---------------------------------------------------------------------------
__global__ void bias_kernel(const float* __restrict__ b1w, const float* __restrict__ b1b,
                            const float* __restrict__ b2w, const float* __restrict__ b2b) {
    __shared__ float h[8 * 32];
    int t = threadIdx.x;
    int b = t >> 5, k = t & 31;
    float s = b1b[k];
    for (int n = 0; n < 32; n++) s += g_pooled[b * 32 + n] * b1w[k * 32 + n];
    h[t] = fmaxf(s, 0.f);
    __syncthreads();
    int m = k;
    float s2 = b2b[m];
    for (int kk = 0; kk < 32; kk++) s2 += h[b * 32 + kk] * b2w[m * 32 + kk];
    g_bias[t] = s2;
}

// ---------------------------------------------------------------------------
// Kernel 3: attention stack via tf32 mma.sync.
// Per 16x16 tile: D[256px, 16(o pad)] GEMM, K=288=(t,n), fragment addressing
// identical to main_kernel. Epilogue (exact fp32): smem transpose of D frags
// (reusing xs space) -> per-thread pixel: relu -> 9x9 -> relu -> 9x9 -> sigmoid.
// ---------------------------------------------------------------------------
__global__ __launch_bounds__(256, 3)
void attn_kernel(const float* __restrict__ x, const float* __restrict__ a1w,
                 const float* __restrict__ a1b, const float* __restrict__ a2w,
                 const float* __restrict__ a2b, const float* __restrict__ a3w,
                 const float* __restrict__ a3b) {
    extern __shared__ uint32_t smu[];
    uint32_t* xs = smu;                  // 32*18*20 = 11520 (tf32); reused as trans64
    uint32_t* w1t = smu + 11520;         // 9*16*36 = 5184   [t][o(pad16)][n(pad36)]
    float* w2 = (float*)(smu + 11520 + 5184);   // 81
    float* w3 = w2 + 81;                 // 81
    float* bb1 = w3 + 81;                // 9
    float* bb2 = bb1 + 9;                // 9
    float* bb3 = bb2 + 9;                // 9

    int b = blockIdx.z;
    int y0 = blockIdx.y * 16, x0 = blockIdx.x * 16;
    int tid = threadIdx.x;

    for (int i = tid; i < 5184; i += 256) {
        int t = i / 576;
        int r = i % 576;
        int o = r / 36, n = r % 36;
        w1t[i] = (o < 9 && n < 32) ? cvt_tf32(a1w[o * 288 + n * 9 + t]) : 0u;
    }
    if (tid < 81) { w2[tid] = a2w[tid]; w3[tid] = a3w[tid]; }
    if (tid < 9) { bb1[tid] = a1b[tid]; bb2[tid] = a2b[tid]; bb3[tid] = a3b[tid]; }

    const float* xb = x + (size_t)b * 32 * Hh * Ww;
    for (int i = tid; i < 32 * 18 * 18; i += 256) {
        int n = i / 324;
        int r = i % 324;
        int yy = r / 18, xx = r % 18;
        int gy = y0 + yy - 1, gx = x0 + xx - 1;
        float v = 0.f;
        if ((unsigned)gy < Hh && (unsigned)gx < Ww) v = xb[(n * Hh + gy) * Ww + gx];
        xs[n * 360 + yy * 20 + xx] = cvt_tf32(v);
    }
    __syncthreads();

    int wid = tid >> 5, lane = tid & 31;
    int r4 = lane >> 2, k0 = lane & 3;
    int yA = 2 * wid;

    float D[2][2][4];
#pragma unroll
    for (int f = 0; f < 2; f++)
#pragma unroll
        for (int oc = 0; oc < 2; oc++)
#pragma unroll
            for (int e = 0; e < 4; e++) D[f][oc][e] = 0.f;

#pragma unroll
    for (int t = 0; t < 9; t++) {
        const int ki = t / 3, kj = t % 3;
        const uint32_t* wsT = w1t + t * 576;
        const uint32_t* xbase0 = xs + k0 * 360 + (yA + ki) * 20 + r4 + kj;
        const uint32_t* xbase1 = xbase0 + 20;
#pragma unroll
        for (int q = 0; q < 4; q++) {
            const uint32_t* xc0 = xbase0 + q * 2880;
            const uint32_t* xc1 = xbase1 + q * 2880;
            uint32_t a0[4], a1[4];
            a0[0] = xc0[0];        a0[1] = xc0[8];
            a0[2] = xc0[4 * 360];  a0[3] = xc0[4 * 360 + 8];
            a1[0] = xc1[0];        a1[1] = xc1[8];
            a1[2] = xc1[4 * 360];  a1[3] = xc1[4 * 360 + 8];
            int n0 = 8 * q + k0;
            const uint32_t* wq = wsT + r4 * 36 + n0;
#pragma unroll
            for (int oc = 0; oc < 2; oc++) {
                uint32_t bb[2];
                bb[0] = wq[oc * 288];       // o = oc*8 + r4, k=n0
                bb[1] = wq[oc * 288 + 4];   // k=n0+4
                mma_tf32(D[0][oc], a0, bb);
                mma_tf32(D[1][oc], a1, bb);
            }
        }
    }

    // transpose D -> per-pixel o-vectors (reuse xs space; 256*9 ull = 18KB)
    __syncthreads();
    ull* tr = (ull*)xs;   // tr[px*9 + pair], pair = oc*4+k0, o = {2*pair, 2*pair+1}
#pragma unroll
    for (int f = 0; f < 2; f++) {
        int yy = yA + f;
#pragma unroll
        for (int oc = 0; oc < 2; oc++) {
            int pr = oc * 4 + k0;
            float2 lo2 = make_float2(D[f][oc][0], D[f][oc][1]);
            float2 hi2 = make_float2(D[f][oc][2], D[f][oc][3]);
            tr[(yy * 16 + r4) * 9 + pr]     = *(ull*)&lo2;
            tr[(yy * 16 + r4 + 8) * 9 + pr] = *(ull*)&hi2;
        }
    }
    __syncthreads();

    // epilogue: one pixel per thread
    {
        int px = tid;
        float u[10], z[9];
#pragma unroll
        for (int j = 0; j < 5; j++) {
            float2 v = *(float2*)&tr[px * 9 + j];
            u[2 * j] = v.x;
            u[2 * j + 1] = v.y;
        }
#pragma unroll
        for (int o = 0; o < 9; o++) u[o] = fmaxf(u[o] + bb1[o], 0.f);
#pragma unroll
        for (int o2 = 0; o2 < 9; o2++) {
            float s = bb2[o2];
#pragma unroll
            for (int o = 0; o < 9; o++) s += w2[o2 * 9 + o] * u[o];
            z[o2] = fmaxf(s, 0.f);
        }
        int gy = y0 + (px >> 4), gx = x0 + (px & 15);
#pragma unroll
        for (int o3 = 0; o3 < 9; o3++) {
            float s = bb3[o3];
#pragma unroll
            for (int o2 = 0; o2 < 9; o2++) s += w3[o3 * 9 + o2] * z[o2];
            float att = 1.f / (1.f + __expf(-s));
            g_att[((b * 9 + o3) * Hh + gy) * Ww + gx] = att;
        }
    }
}

// ---------------------------------------------------------------------------
// Kernel 4: main conv via tf32 mma.sync (unchanged from R5).
// ---------------------------------------------------------------------------
__global__ __launch_bounds__(256, 2)
void main_kernel(const float* __restrict__ x, const float* __restrict__ weight,
                 float* __restrict__ out) {
    extern __shared__ uint32_t smu[];
    uint32_t* xs = smu;                       // 32*18*20 = 11520
    uint32_t* ws = smu + 11520;               // 9*32*36  = 10368
    float* atts = (float*)(smu + 11520 + 10368);  // 2304
    float* sbias = atts + 2304;               // 32

    int tid = threadIdx.x;

    for (int i = tid; i < 9216; i += 256) {
        int p = i >> 10;
        int r = i & 1023;
        int m = r >> 5;
        int n = r & 31;
        ws[p * 1152 + m * 36 + n] = cvt_tf32(weight[(m * 32 + n) * 9 + p]);
    }

    int wid = tid >> 5, lane = tid & 31;
    int r4 = lane >> 2, k0 = lane & 3;

    int tile0 = blockIdx.x * 4;
    for (int t = 0; t < 4; t++) {
        int tile = tile0 + t;
        int b = tile / 144;
        int rr = tile % 144;
        int y0 = (rr / 12) * 16, x0 = (rr % 12) * 16;

        __syncthreads();

        const float* xb = x + (size_t)b * 32 * Hh * Ww;
        for (int i = tid; i < 32 * 18 * 18; i += 256) {
            int n = i / 324;
            int r = i % 324;
            int yy = r / 18, xx = r % 18;
            int gy = y0 + yy - 1, gx = x0 + xx - 1;
            float v = 0.f;
            if ((unsigned)gy < Hh && (unsigned)gx < Ww) v = xb[(n * Hh + gy) * Ww + gx];
            xs[n * 360 + yy * 20 + xx] = cvt_tf32(v);
        }
        for (int i = tid; i < 2304; i += 256) {
            int p = i >> 8;
            int r = i & 255;
            int yy = r >> 4, xx = r & 15;
            atts[i] = g_att[((b * 9 + p) * Hh + y0 + yy) * Ww + x0 + xx];
        }
        if (tid < 32) sbias[tid] = g_bias[b * 32 + tid];
        __syncthreads();

        float D[2][4][4];
#pragma unroll
        for (int f = 0; f < 2; f++)
#pragma unroll
            for (int mc = 0; mc < 4; mc++)
#pragma unroll
                for (int e = 0; e < 4; e++) D[f][mc][e] = 0.f;

        int yA = 2 * wid;

#pragma unroll
        for (int p = 0; p < 9; p++) {
            const int ki = p / 3, kj = p % 3;
            float G[2][4][4];
#pragma unroll
            for (int f = 0; f < 2; f++)
#pragma unroll
                for (int mc = 0; mc < 4; mc++)
#pragma unroll
                    for (int e = 0; e < 4; e++) G[f][mc][e] = 0.f;

            const uint32_t* wsP = ws + p * 1152;
            const uint32_t* xbase0 = xs + k0 * 360 + (yA + ki) * 20 + r4 + kj;
            const uint32_t* xbase1 = xbase0 + 20;
#pragma unroll
            for (int q = 0; q < 4; q++) {
                const uint32_t* xc0 = xbase0 + q * 2880;
                const uint32_t* xc1 = xbase1 + q * 2880;
                uint32_t a0[4], a1[4];
                a0[0] = xc0[0];        a0[1] = xc0[8];
                a0[2] = xc0[4 * 360];  a0[3] = xc0[4 * 360 + 8];
                a1[0] = xc1[0];        a1[1] = xc1[8];
                a1[2] = xc1[4 * 360];  a1[3] = xc1[4 * 360 + 8];
                int n0 = 8 * q + k0;
                const uint32_t* wq = wsP + r4 * 36 + n0;
#pragma unroll
                for (int mc = 0; mc < 4; mc++) {
                    uint32_t bb[2];
                    bb[0] = wq[mc * 288];
                    bb[1] = wq[mc * 288 + 4];
                    mma_tf32(G[0][mc], a0, bb);
                    mma_tf32(G[1][mc], a1, bb);
                }
            }
#pragma unroll
            for (int f = 0; f < 2; f++) {
                int yy = yA + f;
                float attA = atts[(p * 16 + yy) * 16 + r4];
                float attB = atts[(p * 16 + yy) * 16 + r4 + 8];
#pragma unroll
                for (int mc = 0; mc < 4; mc++) {
                    D[f][mc][0] += attA * G[f][mc][0];
                    D[f][mc][1] += attA * G[f][mc][1];
                    D[f][mc][2] += attB * G[f][mc][2];
                    D[f][mc][3] += attB * G[f][mc][3];
                }
            }
        }

#pragma unroll
        for (int f = 0; f < 2; f++) {
            int gy = y0 + yA + f;
#pragma unroll
            for (int mc = 0; mc < 4; mc++) {
                int m = mc * 8 + 2 * k0;
                float bv0 = sbias[m], bv1 = sbias[m + 1];
                float* o0 = out + ((size_t)(b * 32 + m) * Hh + gy) * Ww + x0;
                float* o1 = o0 + (size_t)Hh * Ww;
                o0[r4]     = D[f][mc][0] + bv0;
                o1[r4]     = D[f][mc][1] + bv1;
                o0[r4 + 8] = D[f][mc][2] + bv0;
                o1[r4 + 8] = D[f][mc][3] + bv1;
            }
        }
    }
}

// ---------------------------------------------------------------------------
extern "C" void kernel_launch(void* const* d_in, const int* in_sizes, int n_in,
                              void* d_out, int out_size) {
    const float* x   = (const float*)d_in[0];
    const float* a1w = (const float*)d_in[1];
    const float* a1b = (const float*)d_in[2];
    const float* a2w = (const float*)d_in[3];
    const float* a2b = (const float*)d_in[4];
    const float* a3w = (const float*)d_in[5];
    const float* a3b = (const float*)d_in[6];
    const float* b1w = (const float*)d_in[7];
    const float* b1b = (const float*)d_in[8];
    const float* b2w = (const float*)d_in[9];
    const float* b2b = (const float*)d_in[10];
    const float* wgt = (const float*)d_in[11];
    float* out = (float*)d_out;

    pooled_kernel<<<256, 256>>>(x);
    bias_kernel<<<1, 256>>>(b1w, b1b, b2w, b2b);

    int smA = (11520 + 5184 + 81 + 81 + 9 + 9 + 9 + 3) * (int)sizeof(uint32_t);
    cudaFuncSetAttribute(attn_kernel, cudaFuncAttributeMaxDynamicSharedMemorySize, smA);
    attn_kernel<<<dim3(12, 12, 8), 256, smA>>>(x, a1w, a1b, a2w, a2b, a3w, a3b);

    int smM = (11520 + 10368 + 2304 + 32) * (int)sizeof(uint32_t);
    cudaFuncSetAttribute(main_kernel, cudaFuncAttributeMaxDynamicSharedMemorySize, smM);
    main_kernel<<<288, 256, smM>>>(x, wgt, out);
}

// round 7
// speedup vs baseline: 2.3898x; 1.0158x over previous
#include <cuda_runtime.h>
#include <cstdint>

#define Hh 192
#define Ww 192

__device__ float g_pooled[8 * 32];
__device__ float g_bias[8 * 32];

typedef unsigned long long ull;

__device__ __forceinline__ uint32_t cvt_tf32(float x) {
    uint32_t r; asm("cvt.rna.tf32.f32 %0, %1;" : "=r"(r) : "f"(x)); return r;
}
__device__ __forceinline__ void mma_tf32(float d[4], const uint32_t a[4], const uint32_t b[2]) {
    asm("mma.sync.aligned.m16n8k8.row.col.f32.tf32.tf32.f32 "
        "{%0,%1,%2,%3},{%4,%5,%6,%7},{%8,%9},{%0,%1,%2,%3};"
        : "+f"(d[0]), "+f"(d[1]), "+f"(d[2]), "+f"(d[3])
        : "r"(a[0]), "r"(a[1]), "r"(a[2]), "r"(a[3]), "r"(b[0]), "r"(b[1]));
}

// ---------------------------------------------------------------------------
// Kernel 1: global average pool.
// ---------------------------------------------------------------------------
__global__ void pooled_kernel(const float* __restrict__ x) {
    int bn = blockIdx.x;
    const float* p = x + (size_t)bn * Hh * Ww;
    float s = 0.f;
    for (int i = threadIdx.x; i < Hh * Ww; i += 256) s += p[i];
    __shared__ float red[256];
    red[threadIdx.x] = s;
    __syncthreads();
    for (int o = 128; o > 0; o >>= 1) {
        if (threadIdx.x < o) red[threadIdx.x] += red[threadIdx.x + o];
        __syncthreads();
    }
    if (threadIdx.x == 0) g_pooled[bn] = red[0] * (1.f / (Hh * Ww));
}

// ---------------------------------------------------------------------------
// Kernel 2: bias MLP.
// ---------------------------------------------------------------------------
__global__ void bias_kernel(const float* __restrict__ b1w, const float* __restrict__ b1b,
                            const float* __restrict__ b2w, const float* __restrict__ b2b) {
    __shared__ float h[8 * 32];
    int t = threadIdx.x;
    int b = t >> 5, k = t & 31;
    float s = b1b[k];
    for (int n = 0; n < 32; n++) s += g_pooled[b * 32 + n] * b1w[k * 32 + n];
    h[t] = fmaxf(s, 0.f);
    __syncthreads();
    int m = k;
    float s2 = b2b[m];
    for (int kk = 0; kk < 32; kk++) s2 += h[b * 32 + kk] * b2w[m * 32 + kk];
    g_bias[t] = s2;
}

// ---------------------------------------------------------------------------
// Fused kernel: attention stack + main conv, one 16x32 pair-tile per iter.
// 512 threads = 16 warps; warp w -> tile half (w>>3), rows 2*(w&7).
// smem: xs[2] (tf32, preserved across both mainloops), w1t, ws (filled once),
// tr (attn transpose, overlaid by atts after barrier).
// ---------------------------------------------------------------------------
__global__ __launch_bounds__(512, 1)
void fused_kernel(const float* __restrict__ x, const float* __restrict__ a1w,
                  const float* __restrict__ a1b, const float* __restrict__ a2w,
                  const float* __restrict__ a2b, const float* __restrict__ a3w,
                  const float* __restrict__ a3b, const float* __restrict__ weight,
                  float* __restrict__ out) {
    extern __shared__ uint32_t smu[];
    uint32_t* xs = smu;                     // 2 * 11520 = 23040
    uint32_t* w1t = smu + 23040;            // 9*16*36 = 5184  [t][o16][n36]
    uint32_t* ws = smu + 28224;             // 9*32*36 = 10368 [p][m][n36]
    uint32_t* trbase = smu + 38592;         // 2 * 4608 (tr ull / atts float overlay)
    float* sbias = (float*)(smu + 47808);   // 32
    float* w2 = sbias + 32;                 // 81
    float* w3 = w2 + 81;                    // 81
    float* bb1 = w3 + 81;                   // 9
    float* bb2 = bb1 + 9;                   // 9
    float* bb3 = bb2 + 9;                   // 9

    int tid = threadIdx.x;

    // one-time weight fills
    for (int i = tid; i < 5184; i += 512) {
        int t = i / 576;
        int r = i % 576;
        int o = r / 36, n = r % 36;
        w1t[i] = (o < 9 && n < 32) ? cvt_tf32(a1w[o * 288 + n * 9 + t]) : 0u;
    }
    for (int i = tid; i < 9216; i += 512) {
        int p = i >> 10;
        int r = i & 1023;
        int m = r >> 5;
        int n = r & 31;
        ws[p * 1152 + m * 36 + n] = cvt_tf32(weight[(m * 32 + n) * 9 + p]);
    }
    if (tid < 81) { w2[tid] = a2w[tid]; w3[tid] = a3w[tid]; }
    if (tid < 9) { bb1[tid] = a1b[tid]; bb2[tid] = a2b[tid]; bb3[tid] = a3b[tid]; }

    int wid = tid >> 5, lane = tid & 31;
    int r4 = lane >> 2, k0 = lane & 3;
    int tw = wid >> 3;              // warp's tile half
    int yA = 2 * (wid & 7);

    for (int it = 0; it < 4; it++) {
        int pairIdx = blockIdx.x * 4 + it;
        int b = pairIdx / 72;
        int rr = pairIdx % 72;
        int y0 = (rr / 6) * 16;
        int x0p = (rr % 6) * 32;

        __syncthreads();   // weights ready (it=0) / prev iter smem reads done

        // div-free xs fill: thread -> (tile half, channel, row group)
        {
            int th = tid >> 8;          // tile half
            int tid2 = tid & 255;
            int n = tid2 >> 3, s = tid2 & 7;
            int x0 = x0p + th * 16;
            const float* xb = x + (size_t)(b * 32 + n) * Hh * Ww;
            uint32_t* xst = xs + th * 11520 + n * 360;
            for (int yy = s; yy < 18; yy += 8) {
                int gy = y0 + yy - 1;
                bool yok = (unsigned)gy < Hh;
                uint32_t* row = xst + yy * 20;
                const float* grow = xb + (size_t)gy * Ww + (x0 - 1);
#pragma unroll
                for (int xx = 0; xx < 18; xx++) {
                    int gx = x0 - 1 + xx;
                    float v = (yok && (unsigned)gx < Ww) ? grow[xx] : 0.f;
                    row[xx] = cvt_tf32(v);
                }
            }
        }
        if (tid < 32) sbias[tid] = g_bias[b * 32 + tid];
        __syncthreads();

        const uint32_t* xsT = xs + tw * 11520;

        // ---- attention mainloop (tf32 MMA) ----
        float DA[2][2][4];
#pragma unroll
        for (int f = 0; f < 2; f++)
#pragma unroll
            for (int oc = 0; oc < 2; oc++)
#pragma unroll
                for (int e = 0; e < 4; e++) DA[f][oc][e] = 0.f;

#pragma unroll
        for (int t = 0; t < 9; t++) {
            const int ki = t / 3, kj = t % 3;
            const uint32_t* wsT = w1t + t * 576;
            const uint32_t* xbase0 = xsT + k0 * 360 + (yA + ki) * 20 + r4 + kj;
            const uint32_t* xbase1 = xbase0 + 20;
#pragma unroll
            for (int q = 0; q < 4; q++) {
                const uint32_t* xc0 = xbase0 + q * 2880;
                const uint32_t* xc1 = xbase1 + q * 2880;
                uint32_t a0[4], a1[4];
                a0[0] = xc0[0];        a0[1] = xc0[8];
                a0[2] = xc0[4 * 360];  a0[3] = xc0[4 * 360 + 8];
                a1[0] = xc1[0];        a1[1] = xc1[8];
                a1[2] = xc1[4 * 360];  a1[3] = xc1[4 * 360 + 8];
                int n0 = 8 * q + k0;
                const uint32_t* wq = wsT + r4 * 36 + n0;
#pragma unroll
                for (int oc = 0; oc < 2; oc++) {
                    uint32_t bb[2];
                    bb[0] = wq[oc * 288];
                    bb[1] = wq[oc * 288 + 4];
                    mma_tf32(DA[0][oc], a0, bb);
                    mma_tf32(DA[1][oc], a1, bb);
                }
            }
        }

        // transpose DA -> tr (per-pixel o-pairs)
        {
            ull* tr = (ull*)(trbase + tw * 4608);
#pragma unroll
            for (int f = 0; f < 2; f++) {
                int yy = yA + f;
#pragma unroll
                for (int oc = 0; oc < 2; oc++) {
                    int pr = oc * 4 + k0;
                    float2 lo2 = make_float2(DA[f][oc][0], DA[f][oc][1]);
                    float2 hi2 = make_float2(DA[f][oc][2], DA[f][oc][3]);
                    tr[(yy * 16 + r4) * 9 + pr]     = *(ull*)&lo2;
                    tr[(yy * 16 + r4 + 8) * 9 + pr] = *(ull*)&hi2;
                }
            }
        }
        __syncthreads();

        // attention epilogue: one pixel per thread, exact fp32; atts overlays tr
        {
            int th = tid >> 8;
            int px = tid & 255;
            const ull* trt = (const ull*)(trbase + th * 4608);
            float u[10], z[9], att[9];
#pragma unroll
            for (int j = 0; j < 5; j++) {
                float2 v = *(float2*)&trt[px * 9 + j];
                u[2 * j] = v.x;
                u[2 * j + 1] = v.y;
            }
#pragma unroll
            for (int o = 0; o < 9; o++) u[o] = fmaxf(u[o] + bb1[o], 0.f);
#pragma unroll
            for (int o2 = 0; o2 < 9; o2++) {
                float s = bb2[o2];
#pragma unroll
                for (int o = 0; o < 9; o++) s += w2[o2 * 9 + o] * u[o];
                z[o2] = fmaxf(s, 0.f);
            }
#pragma unroll
            for (int o3 = 0; o3 < 9; o3++) {
                float s = bb3[o3];
#pragma unroll
                for (int o2 = 0; o2 < 9; o2++) s += w3[o3 * 9 + o2] * z[o2];
                att[o3] = 1.f / (1.f + __expf(-s));
            }
            __syncthreads();   // all tr reads done before atts overlay writes
            float* atts_t = (float*)(trbase + th * 4608);   // [p][py][px]
#pragma unroll
            for (int o3 = 0; o3 < 9; o3++) atts_t[o3 * 256 + px] = att[o3];
        }
        __syncthreads();

        // ---- main mainloop (tf32 MMA + exact fp32 attention merge) ----
        const float* atts = (const float*)(trbase + tw * 4608);
        float D[2][4][4];
#pragma unroll
        for (int f = 0; f < 2; f++)
#pragma unroll
            for (int mc = 0; mc < 4; mc++)
#pragma unroll
                for (int e = 0; e < 4; e++) D[f][mc][e] = 0.f;

#pragma unroll
        for (int p = 0; p < 9; p++) {
            const int ki = p / 3, kj = p % 3;
            float G[2][4][4];
#pragma unroll
            for (int f = 0; f < 2; f++)
#pragma unroll
                for (int mc = 0; mc < 4; mc++)
#pragma unroll
                    for (int e = 0; e < 4; e++) G[f][mc][e] = 0.f;

            const uint32_t* wsP = ws + p * 1152;
            const uint32_t* xbase0 = xsT + k0 * 360 + (yA + ki) * 20 + r4 + kj;
            const uint32_t* xbase1 = xbase0 + 20;
#pragma unroll
            for (int q = 0; q < 4; q++) {
                const uint32_t* xc0 = xbase0 + q * 2880;
                const uint32_t* xc1 = xbase1 + q * 2880;
                uint32_t a0[4], a1[4];
                a0[0] = xc0[0];        a0[1] = xc0[8];
                a0[2] = xc0[4 * 360];  a0[3] = xc0[4 * 360 + 8];
                a1[0] = xc1[0];        a1[1] = xc1[8];
                a1[2] = xc1[4 * 360];  a1[3] = xc1[4 * 360 + 8];
                int n0 = 8 * q + k0;
                const uint32_t* wq = wsP + r4 * 36 + n0;
#pragma unroll
                for (int mc = 0; mc < 4; mc++) {
                    uint32_t bb[2];
                    bb[0] = wq[mc * 288];
                    bb[1] = wq[mc * 288 + 4];
                    mma_tf32(G[0][mc], a0, bb);
                    mma_tf32(G[1][mc], a1, bb);
                }
            }
#pragma unroll
            for (int f = 0; f < 2; f++) {
                int yy = yA + f;
                float attA = atts[p * 256 + yy * 16 + r4];
                float attB = atts[p * 256 + yy * 16 + r4 + 8];
#pragma unroll
                for (int mc = 0; mc < 4; mc++) {
                    D[f][mc][0] += attA * G[f][mc][0];
                    D[f][mc][1] += attA * G[f][mc][1];
                    D[f][mc][2] += attB * G[f][mc][2];
                    D[f][mc][3] += attB * G[f][mc][3];
                }
            }
        }

        // store
        {
            int x0 = x0p + tw * 16;
#pragma unroll
            for (int f = 0; f < 2; f++) {
                int gy = y0 + yA + f;
#pragma unroll
                for (int mc = 0; mc < 4; mc++) {
                    int m = mc * 8 + 2 * k0;
                    float bv0 = sbias[m], bv1 = sbias[m + 1];
                    float* o0 = out + ((size_t)(b * 32 + m) * Hh + gy) * Ww + x0;
                    float* o1 = o0 + (size_t)Hh * Ww;
                    o0[r4]     = D[f][mc][0] + bv0;
                    o1[r4]     = D[f][mc][1] + bv1;
                    o0[r4 + 8] = D[f][mc][2] + bv0;
                    o1[r4 + 8] = D[f][mc][3] + bv1;
                }
            }
        }
    }
}

// ---------------------------------------------------------------------------
extern "C" void kernel_launch(void* const* d_in, const int* in_sizes, int n_in,
                              void* d_out, int out_size) {
    const float* x   = (const float*)d_in[0];
    const float* a1w = (const float*)d_in[1];
    const float* a1b = (const float*)d_in[2];
    const float* a2w = (const float*)d_in[3];
    const float* a2b = (const float*)d_in[4];
    const float* a3w = (const float*)d_in[5];
    const float* a3b = (const float*)d_in[6];
    const float* b1w = (const float*)d_in[7];
    const float* b1b = (const float*)d_in[8];
    const float* b2w = (const float*)d_in[9];
    const float* b2b = (const float*)d_in[10];
    const float* wgt = (const float*)d_in[11];
    float* out = (float*)d_out;

    pooled_kernel<<<256, 256>>>(x);
    bias_kernel<<<1, 256>>>(b1w, b1b, b2w, b2b);

    int smF = (47808 + 32 + 81 + 81 + 9 + 9 + 9 + 3) * (int)sizeof(uint32_t);
    cudaFuncSetAttribute(fused_kernel, cudaFuncAttributeMaxDynamicSharedMemorySize, smF);
    fused_kernel<<<144, 512, smF>>>(x, a1w, a1b, a2w, a2b, a3w, a3b, wgt, out);
}